// round 1
// baseline (speedup 1.0000x reference)
#include <cuda_runtime.h>
#include <cstdint>

#define NN 16
#define CC 32
#define HH 224
#define WW 224
#define HW (HH * WW)            // 50176
#define NHW (NN * HW)           // 802816

// ---------------- device scratch (static, no runtime allocation) ----------------
__device__ unsigned  g_bits[NHW];          // packed signs, 1 word per pixel (3.2 MB)
__device__ short     g_y[(size_t)NHW * 32];// conv output, channel-last (51.4 MB)
__device__ long long g_sum[32];
__device__ long long g_ssq[32];
__device__ unsigned  g_wm0[288];           // weight sign masks, layer 1: [o][tap]
__device__ unsigned  g_wm1[288];           // layer 2
__device__ float     g_a[32];              // per-channel affine: bn(v) = a*v + c
__device__ float     g_c[32];

// ---------------- K0: pack weight masks + zero stats ----------------
__global__ void k_prep(const float* __restrict__ w1, const float* __restrict__ w2) {
    int tid = threadIdx.x;   // 608 threads
    if (tid < 288) {
        int o = tid / 9, t = tid % 9;
        unsigned m = 0;
        #pragma unroll
        for (int k = 0; k < 32; k++)
            m |= (w1[(o * 32 + k) * 9 + t] > 0.0f ? 1u : 0u) << k;
        g_wm0[tid] = m;
    } else if (tid < 576) {
        int i = tid - 288;
        int o = i / 9, t = i % 9;
        unsigned m = 0;
        #pragma unroll
        for (int k = 0; k < 32; k++)
            m |= (w2[(o * 32 + k) * 9 + t] > 0.0f ? 1u : 0u) << k;
        g_wm1[i] = m;
    } else if (tid < 608) {
        g_sum[tid - 576] = 0;
        g_ssq[tid - 576] = 0;
    }
}

// ---------------- K1: binarize x -> packed bits ----------------
// grid = NN*HH blocks of WW threads; each thread packs one pixel's 32 channel signs.
__global__ void k_pack_x(const float* __restrict__ x) {
    int n = blockIdx.x / HH;
    int h = blockIdx.x % HH;
    int w = threadIdx.x;
    size_t q = (size_t)h * WW + w;
    unsigned b = 0;
    #pragma unroll
    for (int c = 0; c < 32; c++) {
        float v = x[((size_t)(n * 32 + c)) * HW + q];
        b |= (v > 0.0f ? 1u : 0u) << c;
    }
    g_bits[(size_t)n * HW + q] = b;
}

// ---------------- K2/K5: binarized conv (popcount) + int stats ----------------
// block = (32, 8): x = 32 pixels along w, y = 8 channel-groups of 4 output channels.
// Each block handles one (n, h) row, stepping w in 7 chunks of 32.
__global__ __launch_bounds__(256) void k_conv(bool use2) {
    const unsigned* __restrict__ wm = use2 ? g_wm1 : g_wm0;
    int n = blockIdx.x / HH;
    int h = blockIdx.x % HH;
    int lane = threadIdx.x;          // 0..31
    int cbase = threadIdx.y * 4;     // output channel group

    unsigned m[4][9];
    #pragma unroll
    for (int j = 0; j < 4; j++)
        #pragma unroll
        for (int t = 0; t < 9; t++)
            m[j][t] = wm[(cbase + j) * 9 + t];

    const unsigned* __restrict__ rowB = g_bits + (size_t)n * HW;
    bool okT = (h > 0), okB = (h < HH - 1);

    int rs[4] = {0, 0, 0, 0};
    int rq[4] = {0, 0, 0, 0};

    #pragma unroll 1
    for (int step = 0; step < 7; step++) {
        int w = step * 32 + lane;
        bool okL = (w > 0), okR = (w < WW - 1);
        int base = h * WW + w;

        unsigned xv[9];
        xv[0] = (okT && okL) ? rowB[base - WW - 1] : 0u;
        xv[1] = okT          ? rowB[base - WW]     : 0u;
        xv[2] = (okT && okR) ? rowB[base - WW + 1] : 0u;
        xv[3] = okL          ? rowB[base - 1]      : 0u;
        xv[4] =                rowB[base];
        xv[5] = okR          ? rowB[base + 1]      : 0u;
        xv[6] = (okB && okL) ? rowB[base + WW - 1] : 0u;
        xv[7] = okB          ? rowB[base + WW]     : 0u;
        xv[8] = (okB && okR) ? rowB[base + WW + 1] : 0u;

        bool allok = okT && okB && okL && okR;
        short outv[4];
        #pragma unroll
        for (int j = 0; j < 4; j++) {
            int ps = 0;
            #pragma unroll
            for (int t = 0; t < 9; t++)
                ps += __popc(xv[t] ^ m[j][t]);
            int acc = 288 - 2 * ps;
            if (!allok) {
                // remove the spurious contribution of zero-padded (invalid) taps,
                // which were computed as if xv = 0: each contributed 32-2*popc(m).
                if (!(okT && okL)) acc -= 32 - 2 * __popc(m[j][0]);
                if (!okT)          acc -= 32 - 2 * __popc(m[j][1]);
                if (!(okT && okR)) acc -= 32 - 2 * __popc(m[j][2]);
                if (!okL)          acc -= 32 - 2 * __popc(m[j][3]);
                if (!okR)          acc -= 32 - 2 * __popc(m[j][5]);
                if (!(okB && okL)) acc -= 32 - 2 * __popc(m[j][6]);
                if (!okB)          acc -= 32 - 2 * __popc(m[j][7]);
                if (!(okB && okR)) acc -= 32 - 2 * __popc(m[j][8]);
            }
            outv[j] = (short)acc;
            rs[j] += acc;
            rq[j] += acc * acc;
        }
        size_t off = ((size_t)(n * HW + base)) * 32 + cbase;
        *reinterpret_cast<short4*>(g_y + off) =
            make_short4(outv[0], outv[1], outv[2], outv[3]);
    }

    // warp-level reduction (lanes = 32 pixels of the same channel group)
    #pragma unroll
    for (int j = 0; j < 4; j++) {
        int s = __reduce_add_sync(0xffffffffu, rs[j]);
        int q = __reduce_add_sync(0xffffffffu, rq[j]);
        if (lane == 0) {
            atomicAdd((unsigned long long*)&g_sum[cbase + j],
                      (unsigned long long)(long long)s);
            atomicAdd((unsigned long long*)&g_ssq[cbase + j],
                      (unsigned long long)(long long)q);
        }
    }
}

// ---------------- K3/K6: stats -> per-channel affine, re-zero stats ----------------
__global__ void k_stats(const float* __restrict__ gamma, const float* __restrict__ beta) {
    int o = threadIdx.x;  // 32 threads
    double mean = (double)g_sum[o] / (double)NHW;
    double var  = (double)g_ssq[o] / (double)NHW - mean * mean;
    double inv  = rsqrt(var + 1e-5);
    double a    = (double)gamma[o] * inv;
    g_a[o] = (float)a;
    g_c[o] = (float)((double)beta[o] - mean * a);
    g_sum[o] = 0;
    g_ssq[o] = 0;
}

// ---------------- K4: threshold int16 conv output -> packed bits ----------------
__global__ __launch_bounds__(256) void k_pack_y() {
    __shared__ float sa[32], sc[32];
    int tid = threadIdx.x;
    if (tid < 32) { sa[tid] = g_a[tid]; sc[tid] = g_c[tid]; }
    __syncthreads();
    int p = blockIdx.x * 256 + tid;   // 3136 * 256 == NHW exactly
    const short4* yp = reinterpret_cast<const short4*>(g_y + (size_t)p * 32);
    unsigned b = 0;
    #pragma unroll
    for (int g = 0; g < 8; g++) {
        short4 v = yp[g];
        b |= (fmaf(sa[g*4+0], (float)v.x, sc[g*4+0]) > 0.0f ? 1u : 0u) << (g*4+0);
        b |= (fmaf(sa[g*4+1], (float)v.y, sc[g*4+1]) > 0.0f ? 1u : 0u) << (g*4+1);
        b |= (fmaf(sa[g*4+2], (float)v.z, sc[g*4+2]) > 0.0f ? 1u : 0u) << (g*4+2);
        b |= (fmaf(sa[g*4+3], (float)v.w, sc[g*4+3]) > 0.0f ? 1u : 0u) << (g*4+3);
    }
    g_bits[p] = b;
}

// ---------------- K7: out = x + a2*conv2 + c2 ----------------
__global__ void k_final(const float* __restrict__ x, float* __restrict__ out) {
    __shared__ float sa[32], sc[32];
    int tid = threadIdx.x;  // 224
    if (tid < 32) { sa[tid] = g_a[tid]; sc[tid] = g_c[tid]; }
    __syncthreads();
    int n = blockIdx.x / HH;
    int h = blockIdx.x % HH;
    int w = tid;
    size_t pix = (size_t)n * HW + (size_t)h * WW + w;
    const short4* yp = reinterpret_cast<const short4*>(g_y + pix * 32);
    short4 v4[8];
    #pragma unroll
    for (int g = 0; g < 8; g++) v4[g] = yp[g];
    const short* vs = reinterpret_cast<const short*>(v4);
    size_t q = (size_t)h * WW + w;
    #pragma unroll
    for (int c = 0; c < 32; c++) {
        size_t idx = ((size_t)(n * 32 + c)) * HW + q;
        out[idx] = x[idx] + fmaf(sa[c], (float)vs[c], sc[c]);
    }
}

// ---------------- launch ----------------
extern "C" void kernel_launch(void* const* d_in, const int* in_sizes, int n_in,
                              void* d_out, int out_size) {
    const float* x  = (const float*)d_in[0];
    const float* w1 = (const float*)d_in[1];
    const float* g1 = (const float*)d_in[2];
    const float* b1 = (const float*)d_in[3];
    const float* w2 = (const float*)d_in[4];
    const float* g2 = (const float*)d_in[5];
    const float* b2 = (const float*)d_in[6];
    float* out = (float*)d_out;

    k_prep<<<1, 608>>>(w1, w2);
    k_pack_x<<<NN * HH, WW>>>(x);
    k_conv<<<NN * HH, dim3(32, 8)>>>(false);
    k_stats<<<1, 32>>>(g1, b1);
    k_pack_y<<<NHW / 256, 256>>>();
    k_conv<<<NN * HH, dim3(32, 8)>>>(true);
    k_stats<<<1, 32>>>(g2, b2);
    k_final<<<NN * HH, WW>>>(x, out);
}

// round 2
// speedup vs baseline: 1.0967x; 1.0967x over previous
#include <cuda_runtime.h>
#include <cstdint>

#define NN 16
#define CC 32
#define HH 224
#define WW 224
#define HW (HH * WW)            // 50176
#define NHW (NN * HW)           // 802816
#define PW 226                  // padded width
#define PH 226                  // padded height
#define PHW (PW * PH)           // 51076
#define NPHW (NN * PHW)         // 817216

// ---------------- device scratch (static, no runtime allocation) ----------------
__device__ unsigned  g_bits[NPHW];          // packed signs, padded, 1 word/pixel (3.3 MB)
__device__ short     g_y[(size_t)NHW * 32]; // conv output, channel-last (51.4 MB)
__device__ long long g_sum[32];
__device__ long long g_ssq[32];
__device__ unsigned  g_wm0[288];            // weight sign masks, layer 1: [o][tap]
__device__ unsigned  g_wm1[288];            // layer 2
__device__ float     g_a[32];               // per-channel affine: bn(v) = a*v + c
__device__ float     g_c[32];

// ---------------- K0: zero padded bit image + pack weight masks + zero stats ----
__global__ void k_prep(const float* __restrict__ w1, const float* __restrict__ w2) {
    int gid = blockIdx.x * blockDim.x + threadIdx.x;
    if (gid < NPHW) g_bits[gid] = 0u;       // zero whole padded image (borders matter)
    if (blockIdx.x == 0) {
        int tid = threadIdx.x;
        if (tid < 288) {
            int o = tid / 9, t = tid % 9;
            unsigned m = 0;
            #pragma unroll
            for (int k = 0; k < 32; k++)
                m |= (w1[(o * 32 + k) * 9 + t] > 0.0f ? 1u : 0u) << k;
            g_wm0[tid] = m;
        } else if (tid < 576) {
            int i = tid - 288;
            int o = i / 9, t = i % 9;
            unsigned m = 0;
            #pragma unroll
            for (int k = 0; k < 32; k++)
                m |= (w2[(o * 32 + k) * 9 + t] > 0.0f ? 1u : 0u) << k;
            g_wm1[i] = m;
        } else if (tid < 608) {
            g_sum[tid - 576] = 0;
            g_ssq[tid - 576] = 0;
        }
    }
}

// ---------------- K1: binarize x -> packed bits (interior of padded image) ------
__global__ void k_pack_x(const float* __restrict__ x) {
    int n = blockIdx.x / HH;
    int h = blockIdx.x % HH;
    int w = threadIdx.x;                      // 224
    size_t q = (size_t)h * WW + w;
    unsigned b = 0;
    #pragma unroll
    for (int c = 0; c < 32; c++) {
        float v = x[((size_t)(n * 32 + c)) * HW + q];
        b |= (v > 0.0f ? 1u : 0u) << c;
    }
    g_bits[(size_t)n * PHW + (size_t)(h + 1) * PW + (w + 1)] = b;
}

// ---------------- K2/K5: binarized conv (popcount) + int stats ------------------
// block = (32, 8): x = 32 pixels along w, y = 8 groups of 4 output channels.
// Each block handles one (n, h) output row, stepping w in 7 chunks of 32.
// Padded zero border => all 9 tap loads unconditional; border fixups via
// precomputed additive corrections (zero-word tap contributed 32-2*popc(m),
// true contribution is 0).
__global__ __launch_bounds__(256) void k_conv(int layer) {
    const unsigned* __restrict__ wm = layer ? g_wm1 : g_wm0;
    __shared__ int sEffL[32], sEffR[32];      // column-edge corrections (corner-adjusted)

    int n    = blockIdx.x / HH;
    int h    = blockIdx.x % HH;
    int lane = threadIdx.x;                   // 0..31
    int cb   = threadIdx.y * 4;               // output channel group base

    unsigned m[4][9];
    #pragma unroll
    for (int j = 0; j < 4; j++)
        #pragma unroll
        for (int t = 0; t < 9; t++)
            m[j][t] = wm[(cb + j) * 9 + t];

    bool iT = (h == 0), iB = (h == HH - 1);

    // per-tap spurious contribution c_t = 32 - 2*popc(m_t); corrections are -c_t sums
    int rowc[4];
    #pragma unroll
    for (int j = 0; j < 4; j++) {
        int c[9];
        #pragma unroll
        for (int t = 0; t < 9; t++) c[t] = 32 - 2 * __popc(m[j][t]);
        int rc = 0;
        if (iT) rc -= c[0] + c[1] + c[2];
        if (iB) rc -= c[6] + c[7] + c[8];
        rowc[j] = rc;
        if (lane == 0) {
            int el = -(c[0] + c[3] + c[6]);
            int er = -(c[2] + c[5] + c[8]);
            if (iT) { el += c[0]; er += c[2]; }   // un-double-count corners
            if (iB) { el += c[6]; er += c[8]; }
            sEffL[cb + j] = el;
            sEffR[cb + j] = er;
        }
    }
    __syncthreads();

    const unsigned* __restrict__ bits = g_bits + (size_t)n * PHW;

    int rs[4] = {0, 0, 0, 0};
    int rq[4] = {0, 0, 0, 0};

    #pragma unroll 1
    for (int step = 0; step < 7; step++) {
        int w = step * 32 + lane;
        const unsigned* p = bits + (size_t)h * PW + w;   // top-left tap of output (h,w)

        unsigned x0 = p[0],        x1 = p[1],        x2 = p[2];
        unsigned x3 = p[PW],       x4 = p[PW + 1],   x5 = p[PW + 2];
        unsigned x6 = p[2 * PW],   x7 = p[2 * PW + 1], x8 = p[2 * PW + 2];

        short outv[4];
        #pragma unroll
        for (int j = 0; j < 4; j++) {
            int ps = __popc(x0 ^ m[j][0]) + __popc(x1 ^ m[j][1]) + __popc(x2 ^ m[j][2])
                   + __popc(x3 ^ m[j][3]) + __popc(x4 ^ m[j][4]) + __popc(x5 ^ m[j][5])
                   + __popc(x6 ^ m[j][6]) + __popc(x7 ^ m[j][7]) + __popc(x8 ^ m[j][8]);
            int acc = 288 - 2 * ps + rowc[j];
            if (step == 0 || step == 6) {      // warp-uniform branch
                if (w == 0)      acc += sEffL[cb + j];
                if (w == WW - 1) acc += sEffR[cb + j];
            }
            outv[j] = (short)acc;
            rs[j] += acc;
            rq[j] += acc * acc;
        }
        size_t off = ((size_t)n * HW + (size_t)h * WW + w) * 32 + cb;
        *reinterpret_cast<short4*>(g_y + off) =
            make_short4(outv[0], outv[1], outv[2], outv[3]);
    }

    // warp-level reduction (lanes = 32 pixels of the same channel group)
    #pragma unroll
    for (int j = 0; j < 4; j++) {
        int s = __reduce_add_sync(0xffffffffu, rs[j]);
        int q = __reduce_add_sync(0xffffffffu, rq[j]);
        if (lane == 0) {
            atomicAdd((unsigned long long*)&g_sum[cb + j],
                      (unsigned long long)(long long)s);
            atomicAdd((unsigned long long*)&g_ssq[cb + j],
                      (unsigned long long)(long long)q);
        }
    }
}

// ---------------- K3/K6: stats -> per-channel affine, re-zero stats -------------
__global__ void k_stats(const float* __restrict__ gamma, const float* __restrict__ beta) {
    int o = threadIdx.x;  // 32 threads
    double mean = (double)g_sum[o] / (double)NHW;
    double var  = (double)g_ssq[o] / (double)NHW - mean * mean;
    double inv  = rsqrt(var + 1e-5);
    double a    = (double)gamma[o] * inv;
    g_a[o] = (float)a;
    g_c[o] = (float)((double)beta[o] - mean * a);
    g_sum[o] = 0;
    g_ssq[o] = 0;
}

// ---------------- K4: threshold int16 conv output -> packed bits ----------------
__global__ __launch_bounds__(224) void k_pack_y() {
    __shared__ float sa[32], sc[32];
    int tid = threadIdx.x;                    // 224
    if (tid < 32) { sa[tid] = g_a[tid]; sc[tid] = g_c[tid]; }
    __syncthreads();
    int n = blockIdx.x / HH;
    int h = blockIdx.x % HH;
    int w = tid;
    size_t pix = (size_t)n * HW + (size_t)h * WW + w;
    const short4* yp = reinterpret_cast<const short4*>(g_y + pix * 32);
    unsigned b = 0;
    #pragma unroll
    for (int g = 0; g < 8; g++) {
        short4 v = yp[g];
        b |= (fmaf(sa[g*4+0], (float)v.x, sc[g*4+0]) > 0.0f ? 1u : 0u) << (g*4+0);
        b |= (fmaf(sa[g*4+1], (float)v.y, sc[g*4+1]) > 0.0f ? 1u : 0u) << (g*4+1);
        b |= (fmaf(sa[g*4+2], (float)v.z, sc[g*4+2]) > 0.0f ? 1u : 0u) << (g*4+2);
        b |= (fmaf(sa[g*4+3], (float)v.w, sc[g*4+3]) > 0.0f ? 1u : 0u) << (g*4+3);
    }
    g_bits[(size_t)n * PHW + (size_t)(h + 1) * PW + (w + 1)] = b;
}

// ---------------- K7: out = x + a2*conv2 + c2 -----------------------------------
__global__ __launch_bounds__(224) void k_final(const float* __restrict__ x,
                                               float* __restrict__ out) {
    __shared__ float sa[32], sc[32];
    int tid = threadIdx.x;                    // 224
    if (tid < 32) { sa[tid] = g_a[tid]; sc[tid] = g_c[tid]; }
    __syncthreads();
    int n = blockIdx.x / HH;
    int h = blockIdx.x % HH;
    int w = tid;
    size_t pix = (size_t)n * HW + (size_t)h * WW + w;
    const short4* yp = reinterpret_cast<const short4*>(g_y + pix * 32);
    short4 v4[8];
    #pragma unroll
    for (int g = 0; g < 8; g++) v4[g] = yp[g];
    const short* vs = reinterpret_cast<const short*>(v4);
    size_t q = (size_t)h * WW + w;
    #pragma unroll
    for (int c = 0; c < 32; c++) {
        size_t idx = ((size_t)(n * 32 + c)) * HW + q;
        out[idx] = x[idx] + fmaf(sa[c], (float)vs[c], sc[c]);
    }
}

// ---------------- launch ---------------------------------------------------------
extern "C" void kernel_launch(void* const* d_in, const int* in_sizes, int n_in,
                              void* d_out, int out_size) {
    const float* x  = (const float*)d_in[0];
    const float* w1 = (const float*)d_in[1];
    const float* g1 = (const float*)d_in[2];
    const float* b1 = (const float*)d_in[3];
    const float* w2 = (const float*)d_in[4];
    const float* g2 = (const float*)d_in[5];
    const float* b2 = (const float*)d_in[6];
    float* out = (float*)d_out;

    k_prep<<<(NPHW + 1023) / 1024, 1024>>>(w1, w2);
    k_pack_x<<<NN * HH, WW>>>(x);
    k_conv<<<NN * HH, dim3(32, 8)>>>(0);
    k_stats<<<1, 32>>>(g1, b1);
    k_pack_y<<<NN * HH, 224>>>();
    k_conv<<<NN * HH, dim3(32, 8)>>>(1);
    k_stats<<<1, 32>>>(g2, b2);
    k_final<<<NN * HH, WW>>>(x, out);
}

// round 3
// speedup vs baseline: 1.1882x; 1.0834x over previous
#include <cuda_runtime.h>
#include <cstdint>

#define NN 16
#define CC 32
#define HH 224
#define WW 224
#define HW (HH * WW)            // 50176
#define NHW (NN * HW)           // 802816
#define PW 226                  // padded width
#define PH 226                  // padded height
#define PHW (PW * PH)           // 51076
#define NPHW (NN * PHW)         // 817216
#define RR 8                    // rows per conv block

// ---------------- device scratch ----------------
__device__ unsigned  g_bits[NPHW];          // packed signs, padded (3.3 MB)
__device__ short     g_y[(size_t)NHW * 32]; // conv output, channel-last (51.4 MB)
__device__ long long g_sum1[32], g_ssq1[32];
__device__ long long g_sum2[32], g_ssq2[32];
__device__ unsigned  g_wm0[288];            // weight sign masks: [o][tap]
__device__ unsigned  g_wm1[288];

// ---------------- K0: zero padded bit image + pack masks + zero stats ----------
__global__ void k_prep(const float* __restrict__ w1, const float* __restrict__ w2) {
    int gid = blockIdx.x * blockDim.x + threadIdx.x;
    if (gid < NPHW) g_bits[gid] = 0u;
    if (blockIdx.x == 0) {
        int tid = threadIdx.x;
        if (tid < 288) {
            int o = tid / 9, t = tid % 9;
            unsigned m = 0;
            #pragma unroll
            for (int k = 0; k < 32; k++)
                m |= (w1[(o * 32 + k) * 9 + t] > 0.0f ? 1u : 0u) << k;
            g_wm0[tid] = m;
        } else if (tid < 576) {
            int i = tid - 288;
            int o = i / 9, t = i % 9;
            unsigned m = 0;
            #pragma unroll
            for (int k = 0; k < 32; k++)
                m |= (w2[(o * 32 + k) * 9 + t] > 0.0f ? 1u : 0u) << k;
            g_wm1[i] = m;
        } else if (tid < 608) {
            int o = tid - 576;
            g_sum1[o] = 0; g_ssq1[o] = 0;
            g_sum2[o] = 0; g_ssq2[o] = 0;
        }
    }
}

// ---------------- K1: binarize x -> packed bits (4 pixels/thread) ---------------
__global__ __launch_bounds__(256) void k_pack_x(const float* __restrict__ x) {
    int t = blockIdx.x * 256 + threadIdx.x;       // NHW/4 = 200704 threads
    size_t p0 = (size_t)t * 4;
    int n = (int)(p0 / HW);
    int q = (int)(p0 % HW);
    unsigned b0 = 0, b1 = 0, b2 = 0, b3 = 0;
    #pragma unroll
    for (int c = 0; c < 32; c++) {
        const float4 v = *reinterpret_cast<const float4*>(x + ((size_t)(n * 32 + c) * HW + q));
        b0 |= (v.x > 0.0f ? 1u : 0u) << c;
        b1 |= (v.y > 0.0f ? 1u : 0u) << c;
        b2 |= (v.z > 0.0f ? 1u : 0u) << c;
        b3 |= (v.w > 0.0f ? 1u : 0u) << c;
    }
    int h = q / WW, w = q % WW;                   // 4 pixels stay in one row (224%4==0)
    unsigned* d = g_bits + (size_t)n * PHW + (size_t)(h + 1) * PW + (w + 1);
    d[0] = b0; d[1] = b1; d[2] = b2; d[3] = b3;
}

// ---------------- K2/K4: binarized conv, vertical sweep + register reuse --------
// block (32,8): lane = column within 32-wide strip, warp = 4 output channels.
// Each block: one (n, strip, rowblock) tile of 32 cols x RR rows, all 32 channels.
__global__ __launch_bounds__(256, 2) void k_conv(int layer) {
    const unsigned* __restrict__ wm = layer ? g_wm1 : g_wm0;
    long long* sums = layer ? g_sum2 : g_sum1;
    long long* ssqs = layer ? g_ssq2 : g_ssq1;

    int bid   = blockIdx.x;
    int n     = bid / 196;                        // 7 strips * 28 rowblocks
    int rem   = bid % 196;
    int strip = rem % 7;
    int rb    = rem / 7;
    int w0    = strip * 32;
    int h0    = rb * RR;
    int lane  = threadIdx.x;
    int cb    = threadIdx.y * 4;

    unsigned m[4][9];
    #pragma unroll
    for (int j = 0; j < 4; j++)
        #pragma unroll
        for (int t = 0; t < 9; t++)
            m[j][t] = wm[(cb + j) * 9 + t];

    int w = w0 + lane;
    bool eL = (w == 0), eR = (w == WW - 1);

    // per-lane corrections (spurious zero-word tap contributes ct = 32-2*popc(m))
    int cadd[4], rct[4], rcb_[4];
    #pragma unroll
    for (int j = 0; j < 4; j++) {
        int ct[9];
        #pragma unroll
        for (int t = 0; t < 9; t++) ct[t] = 32 - 2 * __popc(m[j][t]);
        cadd[j] = eL ? -(ct[0] + ct[3] + ct[6]) : (eR ? -(ct[2] + ct[5] + ct[8]) : 0);
        rct[j]  = -(ct[0] + ct[1] + ct[2]) + (eL ? ct[0] : 0) + (eR ? ct[2] : 0);
        rcb_[j] = -(ct[6] + ct[7] + ct[8]) + (eL ? ct[6] : 0) + (eR ? ct[8] : 0);
    }

    const unsigned* bp = g_bits + (size_t)n * PHW + (size_t)h0 * PW + w;
    unsigned x0 = bp[0],  x1 = bp[1],      x2 = bp[2];
    unsigned x3 = bp[PW], x4 = bp[PW + 1], x5 = bp[PW + 2];

    bool top = (h0 == 0), bot = (h0 + RR == HH);
    int rs[4] = {0, 0, 0, 0};
    int rq[4] = {0, 0, 0, 0};

    #pragma unroll
    for (int rr = 0; rr < RR; rr++) {
        const unsigned* qp = bp + (size_t)(rr + 2) * PW;
        unsigned x6 = qp[0], x7 = qp[1], x8 = qp[2];

        short ov[4];
        #pragma unroll
        for (int j = 0; j < 4; j++) {
            int ps = __popc(x0 ^ m[j][0]) + __popc(x1 ^ m[j][1]) + __popc(x2 ^ m[j][2])
                   + __popc(x3 ^ m[j][3]) + __popc(x4 ^ m[j][4]) + __popc(x5 ^ m[j][5])
                   + __popc(x6 ^ m[j][6]) + __popc(x7 ^ m[j][7]) + __popc(x8 ^ m[j][8]);
            int acc = 288 - 2 * ps + cadd[j];
            if (rr == 0 && top)      acc += rct[j];
            if (rr == RR - 1 && bot) acc += rcb_[j];
            ov[j] = (short)acc;
            rs[j] += acc;
            rq[j] += acc * acc;
        }
        size_t off = ((size_t)n * HW + (size_t)(h0 + rr) * WW + w) * 32 + cb;
        *reinterpret_cast<short4*>(g_y + off) = make_short4(ov[0], ov[1], ov[2], ov[3]);

        x0 = x3; x1 = x4; x2 = x5;
        x3 = x6; x4 = x7; x5 = x8;
    }

    #pragma unroll
    for (int j = 0; j < 4; j++) {
        int s = __reduce_add_sync(0xffffffffu, rs[j]);
        int q = __reduce_add_sync(0xffffffffu, rq[j]);
        if (lane == 0) {
            atomicAdd((unsigned long long*)&sums[cb + j], (unsigned long long)(long long)s);
            atomicAdd((unsigned long long*)&ssqs[cb + j], (unsigned long long)(long long)q);
        }
    }
}

// ---------------- per-block affine from exact integer stats ---------------------
__device__ __forceinline__ void affine_from_stats(
    const long long* __restrict__ s, const long long* __restrict__ q2,
    const float* __restrict__ gamma, const float* __restrict__ beta,
    float* sa, float* sc) {
    int o = threadIdx.x;
    if (o < 32) {
        double mean = (double)s[o] / (double)NHW;
        double var  = (double)q2[o] / (double)NHW - mean * mean;
        double inv  = rsqrt(var + 1e-5);
        double a    = (double)gamma[o] * inv;
        sa[o] = (float)a;
        sc[o] = (float)((double)beta[o] - mean * a);
    }
    __syncthreads();
}

// ---------------- K3: threshold conv1 output -> packed bits ---------------------
__global__ __launch_bounds__(256) void k_pack_y(const float* __restrict__ g1,
                                                const float* __restrict__ b1) {
    __shared__ float sa[32], sc[32];
    affine_from_stats(g_sum1, g_ssq1, g1, b1, sa, sc);
    int p = blockIdx.x * 256 + threadIdx.x;       // NHW threads
    const short4* yp = reinterpret_cast<const short4*>(g_y + (size_t)p * 32);
    unsigned b = 0;
    #pragma unroll
    for (int g = 0; g < 8; g++) {
        short4 v = yp[g];
        b |= (fmaf(sa[g*4+0], (float)v.x, sc[g*4+0]) > 0.0f ? 1u : 0u) << (g*4+0);
        b |= (fmaf(sa[g*4+1], (float)v.y, sc[g*4+1]) > 0.0f ? 1u : 0u) << (g*4+1);
        b |= (fmaf(sa[g*4+2], (float)v.z, sc[g*4+2]) > 0.0f ? 1u : 0u) << (g*4+2);
        b |= (fmaf(sa[g*4+3], (float)v.w, sc[g*4+3]) > 0.0f ? 1u : 0u) << (g*4+3);
    }
    int n = p / HW, q = p % HW;
    int h = q / WW, w = q % WW;
    g_bits[(size_t)n * PHW + (size_t)(h + 1) * PW + (w + 1)] = b;
}

// ---------------- K5: out = x + a2*conv2 + c2 (4 pixels/thread) -----------------
__global__ __launch_bounds__(256) void k_final(const float* __restrict__ x,
                                               const float* __restrict__ g2,
                                               const float* __restrict__ b2,
                                               float* __restrict__ out) {
    __shared__ float sa[32], sc[32];
    affine_from_stats(g_sum2, g_ssq2, g2, b2, sa, sc);
    int t = blockIdx.x * 256 + threadIdx.x;       // NHW/4 threads
    size_t p0 = (size_t)t * 4;
    int n = (int)(p0 / HW);
    int q = (int)(p0 % HW);
    const short* yb = g_y + p0 * 32;

    #pragma unroll
    for (int g = 0; g < 8; g++) {
        short4 y0 = *reinterpret_cast<const short4*>(yb + 0 * 32 + g * 4);
        short4 y1 = *reinterpret_cast<const short4*>(yb + 1 * 32 + g * 4);
        short4 y2 = *reinterpret_cast<const short4*>(yb + 2 * 32 + g * 4);
        short4 y3 = *reinterpret_cast<const short4*>(yb + 3 * 32 + g * 4);

#define DO_CH(COMP, OFF)                                                          \
        {                                                                         \
            int c = g * 4 + OFF;                                                  \
            float a = sa[c], cc = sc[c];                                          \
            size_t xi = (size_t)(n * 32 + c) * HW + q;                            \
            float4 xv = *reinterpret_cast<const float4*>(x + xi);                 \
            float4 o4;                                                            \
            o4.x = xv.x + fmaf(a, (float)y0.COMP, cc);                            \
            o4.y = xv.y + fmaf(a, (float)y1.COMP, cc);                            \
            o4.z = xv.z + fmaf(a, (float)y2.COMP, cc);                            \
            o4.w = xv.w + fmaf(a, (float)y3.COMP, cc);                            \
            *reinterpret_cast<float4*>(out + xi) = o4;                            \
        }
        DO_CH(x, 0)
        DO_CH(y, 1)
        DO_CH(z, 2)
        DO_CH(w, 3)
#undef DO_CH
    }
}

// ---------------- launch ---------------------------------------------------------
extern "C" void kernel_launch(void* const* d_in, const int* in_sizes, int n_in,
                              void* d_out, int out_size) {
    const float* x  = (const float*)d_in[0];
    const float* w1 = (const float*)d_in[1];
    const float* g1 = (const float*)d_in[2];
    const float* b1 = (const float*)d_in[3];
    const float* w2 = (const float*)d_in[4];
    const float* g2 = (const float*)d_in[5];
    const float* b2 = (const float*)d_in[6];
    float* out = (float*)d_out;

    k_prep<<<(NPHW + 1023) / 1024, 1024>>>(w1, w2);
    k_pack_x<<<NHW / 4 / 256, 256>>>(x);
    k_conv<<<NN * 7 * (HH / RR), dim3(32, 8)>>>(0);
    k_pack_y<<<NHW / 256, 256>>>(g1, b1);
    k_conv<<<NN * 7 * (HH / RR), dim3(32, 8)>>>(1);
    k_final<<<NHW / 4 / 256, 256>>>(x, g2, b2, out);
}

// round 4
// speedup vs baseline: 1.2927x; 1.0879x over previous
#include <cuda_runtime.h>
#include <cstdint>

#define NN 16
#define CC 32
#define HH 224
#define WW 224
#define HW (HH * WW)            // 50176
#define NHW (NN * HW)           // 802816
#define PW 226                  // padded width
#define PH 226
#define PHW (PW * PH)           // 51076
#define NPHW (NN * PHW)         // 817216
#define RR 8                    // rows per conv block

// g_y layout: [n][h][group(8)][w][4ch] shorts — group-blocked channel-last.
#define GY_IDX(n, h, g, w) (((((size_t)(n) * HH + (h)) * 8 + (g)) * WW + (w)) * 4)

// ---------------- device scratch ----------------
__device__ unsigned  g_bits[NPHW];
__device__ short     g_y[(size_t)NHW * 32];
__device__ long long g_sum1[32], g_ssq1[32];
__device__ long long g_sum2[32], g_ssq2[32];
__device__ unsigned  g_wm0[288];
__device__ unsigned  g_wm1[288];

// ---------------- K0: zero padded bit image + pack masks + zero stats ----------
__global__ void k_prep(const float* __restrict__ w1, const float* __restrict__ w2) {
    int gid = blockIdx.x * blockDim.x + threadIdx.x;
    if (gid < NPHW) g_bits[gid] = 0u;
    if (blockIdx.x == 0) {
        int tid = threadIdx.x;
        if (tid < 288) {
            int o = tid / 9, t = tid % 9;
            unsigned m = 0;
            #pragma unroll
            for (int k = 0; k < 32; k++)
                m |= (w1[(o * 32 + k) * 9 + t] > 0.0f ? 1u : 0u) << k;
            g_wm0[tid] = m;
        } else if (tid < 576) {
            int i = tid - 288;
            int o = i / 9, t = i % 9;
            unsigned m = 0;
            #pragma unroll
            for (int k = 0; k < 32; k++)
                m |= (w2[(o * 32 + k) * 9 + t] > 0.0f ? 1u : 0u) << k;
            g_wm1[i] = m;
        } else if (tid < 608) {
            int o = tid - 576;
            g_sum1[o] = 0; g_ssq1[o] = 0;
            g_sum2[o] = 0; g_ssq2[o] = 0;
        }
    }
}

// ---------------- K1: binarize x -> packed bits (4 pixels/thread) ---------------
__global__ __launch_bounds__(256) void k_pack_x(const float* __restrict__ x) {
    int t = blockIdx.x * 256 + threadIdx.x;
    size_t p0 = (size_t)t * 4;
    int n = (int)(p0 / HW);
    int q = (int)(p0 % HW);
    unsigned b0 = 0, b1 = 0, b2 = 0, b3 = 0;
    #pragma unroll
    for (int c = 0; c < 32; c++) {
        const float4 v = *reinterpret_cast<const float4*>(x + ((size_t)(n * 32 + c) * HW + q));
        b0 |= (v.x > 0.0f ? 1u : 0u) << c;
        b1 |= (v.y > 0.0f ? 1u : 0u) << c;
        b2 |= (v.z > 0.0f ? 1u : 0u) << c;
        b3 |= (v.w > 0.0f ? 1u : 0u) << c;
    }
    int h = q / WW, w = q % WW;
    unsigned* d = g_bits + (size_t)n * PHW + (size_t)(h + 1) * PW + (w + 1);
    d[0] = b0; d[1] = b1; d[2] = b2; d[3] = b3;
}

// ---------------- K2/K4: binarized conv, vertical sweep + register reuse --------
__global__ __launch_bounds__(256, 2) void k_conv(int layer) {
    const unsigned* __restrict__ wm = layer ? g_wm1 : g_wm0;
    long long* sums = layer ? g_sum2 : g_sum1;
    long long* ssqs = layer ? g_ssq2 : g_ssq1;

    int bid   = blockIdx.x;
    int n     = bid / 196;
    int rem   = bid % 196;
    int strip = rem % 7;
    int rb    = rem / 7;
    int w0    = strip * 32;
    int h0    = rb * RR;
    int lane  = threadIdx.x;
    int g     = threadIdx.y;              // channel group 0..7
    int cb    = g * 4;

    unsigned m[4][9];
    #pragma unroll
    for (int j = 0; j < 4; j++)
        #pragma unroll
        for (int t = 0; t < 9; t++)
            m[j][t] = wm[(cb + j) * 9 + t];

    int w = w0 + lane;
    bool eL = (w == 0), eR = (w == WW - 1);

    int cadd[4], rct[4], rcb_[4];
    #pragma unroll
    for (int j = 0; j < 4; j++) {
        int ct[9];
        #pragma unroll
        for (int t = 0; t < 9; t++) ct[t] = 32 - 2 * __popc(m[j][t]);
        cadd[j] = eL ? -(ct[0] + ct[3] + ct[6]) : (eR ? -(ct[2] + ct[5] + ct[8]) : 0);
        rct[j]  = -(ct[0] + ct[1] + ct[2]) + (eL ? ct[0] : 0) + (eR ? ct[2] : 0);
        rcb_[j] = -(ct[6] + ct[7] + ct[8]) + (eL ? ct[6] : 0) + (eR ? ct[8] : 0);
    }

    const unsigned* bp = g_bits + (size_t)n * PHW + (size_t)h0 * PW + w;
    unsigned x0 = bp[0],  x1 = bp[1],      x2 = bp[2];
    unsigned x3 = bp[PW], x4 = bp[PW + 1], x5 = bp[PW + 2];

    bool top = (h0 == 0), bot = (h0 + RR == HH);
    int rs[4] = {0, 0, 0, 0};
    int rq[4] = {0, 0, 0, 0};

    #pragma unroll
    for (int rr = 0; rr < RR; rr++) {
        const unsigned* qp = bp + (size_t)(rr + 2) * PW;
        unsigned x6 = qp[0], x7 = qp[1], x8 = qp[2];

        short ov[4];
        #pragma unroll
        for (int j = 0; j < 4; j++) {
            int ps = __popc(x0 ^ m[j][0]) + __popc(x1 ^ m[j][1]) + __popc(x2 ^ m[j][2])
                   + __popc(x3 ^ m[j][3]) + __popc(x4 ^ m[j][4]) + __popc(x5 ^ m[j][5])
                   + __popc(x6 ^ m[j][6]) + __popc(x7 ^ m[j][7]) + __popc(x8 ^ m[j][8]);
            int acc = 288 - 2 * ps + cadd[j];
            if (rr == 0 && top)      acc += rct[j];
            if (rr == RR - 1 && bot) acc += rcb_[j];
            ov[j] = (short)acc;
            rs[j] += acc;
            rq[j] += acc * acc;
        }
        // group-blocked store: lane-contiguous 8B => 256B coalesced per warp
        *reinterpret_cast<short4*>(g_y + GY_IDX(n, h0 + rr, g, w)) =
            make_short4(ov[0], ov[1], ov[2], ov[3]);

        x0 = x3; x1 = x4; x2 = x5;
        x3 = x6; x4 = x7; x5 = x8;
    }

    #pragma unroll
    for (int j = 0; j < 4; j++) {
        int s = __reduce_add_sync(0xffffffffu, rs[j]);
        int q = __reduce_add_sync(0xffffffffu, rq[j]);
        if (lane == 0) {
            atomicAdd((unsigned long long*)&sums[cb + j], (unsigned long long)(long long)s);
            atomicAdd((unsigned long long*)&ssqs[cb + j], (unsigned long long)(long long)q);
        }
    }
}

// ---------------- per-block affine from exact integer stats ---------------------
__device__ __forceinline__ void affine_from_stats(
    const long long* __restrict__ s, const long long* __restrict__ q2,
    const float* __restrict__ gamma, const float* __restrict__ beta,
    float* sa, float* sc) {
    int o = threadIdx.x;
    if (o < 32) {
        double mean = (double)s[o] / (double)NHW;
        double var  = (double)q2[o] / (double)NHW - mean * mean;
        double inv  = rsqrt(var + 1e-5);
        double a    = (double)gamma[o] * inv;
        sa[o] = (float)a;
        sc[o] = (float)((double)beta[o] - mean * a);
    }
    __syncthreads();
}

// ---------------- K3: threshold conv1 output -> packed bits (2 px/thread) -------
__global__ __launch_bounds__(256) void k_pack_y(const float* __restrict__ g1,
                                                const float* __restrict__ b1) {
    __shared__ float sa[32], sc[32];
    affine_from_stats(g_sum1, g_ssq1, g1, b1, sa, sc);
    int t = blockIdx.x * 256 + threadIdx.x;       // NHW/2 threads
    size_t p0 = (size_t)t * 2;
    int n = (int)(p0 / HW);
    int q = (int)(p0 % HW);
    int h = q / WW, w = q % WW;                   // w even, both px in same row
    unsigned b0 = 0, b1_ = 0;
    #pragma unroll
    for (int g = 0; g < 8; g++) {
        union { uint4 u; short s[8]; } A;
        A.u = *reinterpret_cast<const uint4*>(g_y + GY_IDX(n, h, g, w));
        #pragma unroll
        for (int j = 0; j < 4; j++) {
            int c = g * 4 + j;
            b0  |= (fmaf(sa[c], (float)A.s[j],     sc[c]) > 0.0f ? 1u : 0u) << c;
            b1_ |= (fmaf(sa[c], (float)A.s[4 + j], sc[c]) > 0.0f ? 1u : 0u) << c;
        }
    }
    unsigned* d = g_bits + (size_t)n * PHW + (size_t)(h + 1) * PW + (w + 1);
    d[0] = b0; d[1] = b1_;
}

// ---------------- K5: out = x + a2*conv2 + c2 (4 px/thread, 16B loads) ----------
__global__ __launch_bounds__(256) void k_final(const float* __restrict__ x,
                                               const float* __restrict__ g2,
                                               const float* __restrict__ b2,
                                               float* __restrict__ out) {
    __shared__ float sa[32], sc[32];
    affine_from_stats(g_sum2, g_ssq2, g2, b2, sa, sc);
    int t = blockIdx.x * 256 + threadIdx.x;       // NHW/4 threads
    size_t p0 = (size_t)t * 4;
    int n = (int)(p0 / HW);
    int q = (int)(p0 % HW);
    int h = q / WW, w = q % WW;                   // w % 4 == 0, all px same row

    #pragma unroll
    for (int g = 0; g < 8; g++) {
        union { uint4 u; short s[8]; } A, B;
        A.u = *reinterpret_cast<const uint4*>(g_y + GY_IDX(n, h, g, w));
        B.u = *reinterpret_cast<const uint4*>(g_y + GY_IDX(n, h, g, w + 2));
        #pragma unroll
        for (int j = 0; j < 4; j++) {
            int c = g * 4 + j;
            float a = sa[c], cc = sc[c];
            size_t xi = (size_t)(n * 32 + c) * HW + q;
            float4 xv = *reinterpret_cast<const float4*>(x + xi);
            float4 o4;
            o4.x = xv.x + fmaf(a, (float)A.s[j],     cc);
            o4.y = xv.y + fmaf(a, (float)A.s[4 + j], cc);
            o4.z = xv.z + fmaf(a, (float)B.s[j],     cc);
            o4.w = xv.w + fmaf(a, (float)B.s[4 + j], cc);
            *reinterpret_cast<float4*>(out + xi) = o4;
        }
    }
}

// ---------------- launch ---------------------------------------------------------
extern "C" void kernel_launch(void* const* d_in, const int* in_sizes, int n_in,
                              void* d_out, int out_size) {
    const float* x  = (const float*)d_in[0];
    const float* w1 = (const float*)d_in[1];
    const float* g1 = (const float*)d_in[2];
    const float* b1 = (const float*)d_in[3];
    const float* w2 = (const float*)d_in[4];
    const float* g2 = (const float*)d_in[5];
    const float* b2 = (const float*)d_in[6];
    float* out = (float*)d_out;

    k_prep<<<(NPHW + 1023) / 1024, 1024>>>(w1, w2);
    k_pack_x<<<NHW / 4 / 256, 256>>>(x);
    k_conv<<<NN * 7 * (HH / RR), dim3(32, 8)>>>(0);
    k_pack_y<<<NHW / 2 / 256, 256>>>(g1, b1);
    k_conv<<<NN * 7 * (HH / RR), dim3(32, 8)>>>(1);
    k_final<<<NHW / 4 / 256, 256>>>(x, g2, b2, out);
}

// round 6
// speedup vs baseline: 1.3466x; 1.0418x over previous
#include <cuda_runtime.h>
#include <cstdint>

#define NN 16
#define CC 32
#define HH 224
#define WW 224
#define HW (HH * WW)            // 50176
#define NHW (NN * HW)           // 802816
#define PW 226
#define PH 226
#define PHW (PW * PH)           // 51076
#define NPHW (NN * PHW)         // 817216
#define RR 8

// g_y layout: [n][h][group(8)][w][4ch] int8 (halved conv values).
#define GY_IDX(n, h, g, w) (((((size_t)(n) * HH + (h)) * 8 + (g)) * WW + (w)) * 4)

// ---------------- device scratch ----------------
__device__ unsigned  g_bits[NPHW];
__device__ signed char g_y[(size_t)NHW * 32];   // 25.7 MB
__device__ long long g_sum1[32], g_ssq1[32];    // stats of HALVED values
__device__ long long g_sum2[32], g_ssq2[32];
__device__ unsigned  g_wm0[288];
__device__ unsigned  g_wm1[288];

// ---------------- K0: zero BORDERS of padded bit image + masks + stats ----------
// Interior (rows 1..224, cols 1..224 of each image) is fully overwritten by
// k_pack_x before any conv reads it, so only borders need zeroing (replay-safe).
__global__ void k_prep(const float* __restrict__ w1, const float* __restrict__ w2) {
    int i = blockIdx.x * blockDim.x + threadIdx.x;
    // 900 border cells per image: top 226, bottom 226, left 224, right 224
    if (i < NN * 900) {
        int img = i / 900, r = i % 900;
        int h, w;
        if (r < 226)      { h = 0;            w = r; }
        else if (r < 452) { h = 225;          w = r - 226; }
        else if (r < 676) { h = r - 452 + 1;  w = 0; }
        else              { h = r - 676 + 1;  w = 225; }
        g_bits[(size_t)img * PHW + (size_t)h * PW + w] = 0u;
    }
    if (blockIdx.x == 0) {
        int tid = threadIdx.x;
        if (tid < 288) {
            int o = tid / 9, t = tid % 9;
            unsigned m = 0;
            #pragma unroll
            for (int k = 0; k < 32; k++)
                m |= (w1[(o * 32 + k) * 9 + t] > 0.0f ? 1u : 0u) << k;
            g_wm0[tid] = m;
        } else if (tid < 576) {
            int j = tid - 288;
            int o = j / 9, t = j % 9;
            unsigned m = 0;
            #pragma unroll
            for (int k = 0; k < 32; k++)
                m |= (w2[(o * 32 + k) * 9 + t] > 0.0f ? 1u : 0u) << k;
            g_wm1[j] = m;
        } else if (tid < 608) {
            int o = tid - 576;
            g_sum1[o] = 0; g_ssq1[o] = 0;
            g_sum2[o] = 0; g_ssq2[o] = 0;
        }
    }
}

// ---------------- K1: binarize x -> packed bits ----------------
__global__ __launch_bounds__(256) void k_pack_x(const float* __restrict__ x) {
    int t = blockIdx.x * 256 + threadIdx.x;
    size_t p0 = (size_t)t * 4;
    int n = (int)(p0 / HW);
    int q = (int)(p0 % HW);
    unsigned b0 = 0, b1 = 0, b2 = 0, b3 = 0;
    #pragma unroll
    for (int c = 0; c < 32; c++) {
        const float4 v = *reinterpret_cast<const float4*>(x + ((size_t)(n * 32 + c) * HW + q));
        b0 |= (v.x > 0.0f ? 1u : 0u) << c;
        b1 |= (v.y > 0.0f ? 1u : 0u) << c;
        b2 |= (v.z > 0.0f ? 1u : 0u) << c;
        b3 |= (v.w > 0.0f ? 1u : 0u) << c;
    }
    int h = q / WW, w = q % WW;
    unsigned* d = g_bits + (size_t)n * PHW + (size_t)(h + 1) * PW + (w + 1);
    d[0] = b0; d[1] = b1; d[2] = b2; d[3] = b3;
}

// ---------------- K2/K4: binarized conv, stores HALVED int8 ----------------
__global__ __launch_bounds__(256, 2) void k_conv(int layer) {
    const unsigned* __restrict__ wm = layer ? g_wm1 : g_wm0;
    long long* sums = layer ? g_sum2 : g_sum1;
    long long* ssqs = layer ? g_ssq2 : g_ssq1;

    int bid   = blockIdx.x;
    int n     = bid / 196;
    int rem   = bid % 196;
    int strip = rem % 7;
    int rb    = rem / 7;
    int w0    = strip * 32;
    int h0    = rb * RR;
    int lane  = threadIdx.x;
    int g     = threadIdx.y;
    int cb    = g * 4;

    unsigned m[4][9];
    #pragma unroll
    for (int j = 0; j < 4; j++)
        #pragma unroll
        for (int t = 0; t < 9; t++)
            m[j][t] = wm[(cb + j) * 9 + t];

    int w = w0 + lane;
    bool eL = (w == 0), eR = (w == WW - 1);

    int cadd[4], rct[4], rcb_[4];
    #pragma unroll
    for (int j = 0; j < 4; j++) {
        int ct[9];
        #pragma unroll
        for (int t = 0; t < 9; t++) ct[t] = 32 - 2 * __popc(m[j][t]);
        cadd[j] = eL ? -(ct[0] + ct[3] + ct[6]) : (eR ? -(ct[2] + ct[5] + ct[8]) : 0);
        rct[j]  = -(ct[0] + ct[1] + ct[2]) + (eL ? ct[0] : 0) + (eR ? ct[2] : 0);
        rcb_[j] = -(ct[6] + ct[7] + ct[8]) + (eL ? ct[6] : 0) + (eR ? ct[8] : 0);
    }

    const unsigned* bp = g_bits + (size_t)n * PHW + (size_t)h0 * PW + w;
    unsigned x0 = bp[0],  x1 = bp[1],      x2 = bp[2];
    unsigned x3 = bp[PW], x4 = bp[PW + 1], x5 = bp[PW + 2];

    bool top = (h0 == 0), bot = (h0 + RR == HH);
    int rs[4] = {0, 0, 0, 0};
    int rq[4] = {0, 0, 0, 0};

    #pragma unroll
    for (int rr = 0; rr < RR; rr++) {
        const unsigned* qp = bp + (size_t)(rr + 2) * PW;
        unsigned x6 = qp[0], x7 = qp[1], x8 = qp[2];

        int hv[4];
        #pragma unroll
        for (int j = 0; j < 4; j++) {
            int ps = __popc(x0 ^ m[j][0]) + __popc(x1 ^ m[j][1]) + __popc(x2 ^ m[j][2])
                   + __popc(x3 ^ m[j][3]) + __popc(x4 ^ m[j][4]) + __popc(x5 ^ m[j][5])
                   + __popc(x6 ^ m[j][6]) + __popc(x7 ^ m[j][7]) + __popc(x8 ^ m[j][8]);
            int acc = 288 - 2 * ps + cadd[j];
            if (rr == 0 && top)      acc += rct[j];
            if (rr == RR - 1 && bot) acc += rcb_[j];
            int h2 = acc >> 1;                 // acc always even; |h2| small
            hv[j] = h2;
            rs[j] += h2;
            rq[j] += h2 * h2;
        }
        *reinterpret_cast<char4*>(g_y + GY_IDX(n, h0 + rr, g, w)) =
            make_char4((signed char)hv[0], (signed char)hv[1],
                       (signed char)hv[2], (signed char)hv[3]);

        x0 = x3; x1 = x4; x2 = x5;
        x3 = x6; x4 = x7; x5 = x8;
    }

    #pragma unroll
    for (int j = 0; j < 4; j++) {
        int s = __reduce_add_sync(0xffffffffu, rs[j]);
        int q = __reduce_add_sync(0xffffffffu, rq[j]);
        if (lane == 0) {
            atomicAdd((unsigned long long*)&sums[cb + j], (unsigned long long)(long long)s);
            atomicAdd((unsigned long long*)&ssqs[cb + j], (unsigned long long)(long long)q);
        }
    }
}

// ---------------- K3: SIMD threshold conv1 (4 px/thread) ----------------
__global__ __launch_bounds__(256) void k_pack_y(const float* __restrict__ gamma,
                                                const float* __restrict__ beta) {
    __shared__ int      sTc[32];
    __shared__ unsigned sFl[32];
    __shared__ unsigned sT[8], sF[8];
    int o = threadIdx.x;
    if (o < 32) {
        double mean = 2.0 * (double)g_sum1[o] / (double)NHW;
        double var  = 4.0 * (double)g_ssq1[o] / (double)NHW - mean * mean;
        double inv  = rsqrt(var + 1e-5);
        double a    = (double)gamma[o] * inv;
        double cst  = (double)beta[o] - mean * a;
        int T; unsigned f;
        if (a > 0.0)      { T = (int)floor(-cst / (2.0 * a));    f = 0x00u; }
        else if (a < 0.0) { T = (int)ceil(-cst / (2.0 * a)) - 1; f = 0xFFu; }
        else              { T = (cst > 0.0) ? -128 : 127;        f = (cst > 0.0) ? 0x00u : 0x00u; }
        T = max(-128, min(127, T));
        sTc[o] = T & 0xFF;
        sFl[o] = f;
    }
    __syncthreads();
    if (o < 8) {
        sT[o] = (unsigned)sTc[4*o] | ((unsigned)sTc[4*o+1] << 8)
              | ((unsigned)sTc[4*o+2] << 16) | ((unsigned)sTc[4*o+3] << 24);
        sF[o] = sFl[4*o] | (sFl[4*o+1] << 8) | (sFl[4*o+2] << 16) | (sFl[4*o+3] << 24);
    }
    __syncthreads();

    int t = blockIdx.x * 256 + threadIdx.x;       // NHW/4 threads
    size_t p0 = (size_t)t * 4;
    int n = (int)(p0 / HW);
    int q = (int)(p0 % HW);
    int h = q / WW, w = q % WW;                   // w % 4 == 0

    unsigned b0 = 0, b1 = 0, b2 = 0, b3 = 0;
    #pragma unroll
    for (int g = 0; g < 8; g++) {
        uint4 A = *reinterpret_cast<const uint4*>(g_y + GY_IDX(n, h, g, w));
        unsigned Tg = sT[g], Fg = sF[g];
        unsigned m0 = (__vcmpgts4(A.x, Tg) ^ Fg) & 0x01010101u;
        unsigned m1 = (__vcmpgts4(A.y, Tg) ^ Fg) & 0x01010101u;
        unsigned m2 = (__vcmpgts4(A.z, Tg) ^ Fg) & 0x01010101u;
        unsigned m3 = (__vcmpgts4(A.w, Tg) ^ Fg) & 0x01010101u;
        b0 |= __dp4a(m0, 0x08040201u, 0u) << (g * 4);
        b1 |= __dp4a(m1, 0x08040201u, 0u) << (g * 4);
        b2 |= __dp4a(m2, 0x08040201u, 0u) << (g * 4);
        b3 |= __dp4a(m3, 0x08040201u, 0u) << (g * 4);
    }
    unsigned* d = g_bits + (size_t)n * PHW + (size_t)(h + 1) * PW + (w + 1);
    d[0] = b0; d[1] = b1; d[2] = b2; d[3] = b3;
}

// ---------------- K5: out = x + a2*(2*yh) + c2 (4 px/thread) ----------------
__global__ __launch_bounds__(256) void k_final(const float* __restrict__ x,
                                               const float* __restrict__ gamma,
                                               const float* __restrict__ beta,
                                               float* __restrict__ out) {
    __shared__ float sa[32], sc[32];
    int o = threadIdx.x;
    if (o < 32) {
        double mean = 2.0 * (double)g_sum2[o] / (double)NHW;
        double var  = 4.0 * (double)g_ssq2[o] / (double)NHW - mean * mean;
        double inv  = rsqrt(var + 1e-5);
        double a    = (double)gamma[o] * inv;
        sa[o] = (float)(2.0 * a);                 // fold the halving back in
        sc[o] = (float)((double)beta[o] - mean * a);
    }
    __syncthreads();

    int t = blockIdx.x * 256 + threadIdx.x;       // NHW/4 threads
    size_t p0 = (size_t)t * 4;
    int n = (int)(p0 / HW);
    int q = (int)(p0 % HW);
    int h = q / WW, w = q % WW;                   // w % 4 == 0

    #pragma unroll
    for (int g = 0; g < 8; g++) {
        union { uint4 u; signed char s[16]; } A;   // signed char: aarch64 plain char is unsigned!
        A.u = *reinterpret_cast<const uint4*>(g_y + GY_IDX(n, h, g, w));
        #pragma unroll
        for (int j = 0; j < 4; j++) {
            int c = g * 4 + j;
            float a = sa[c], cc = sc[c];
            size_t xi = (size_t)(n * 32 + c) * HW + q;
            float4 xv = *reinterpret_cast<const float4*>(x + xi);
            float4 o4;
            o4.x = xv.x + fmaf(a, (float)A.s[0 + j],  cc);
            o4.y = xv.y + fmaf(a, (float)A.s[4 + j],  cc);
            o4.z = xv.z + fmaf(a, (float)A.s[8 + j],  cc);
            o4.w = xv.w + fmaf(a, (float)A.s[12 + j], cc);
            *reinterpret_cast<float4*>(out + xi) = o4;
        }
    }
}

// ---------------- launch ----------------
extern "C" void kernel_launch(void* const* d_in, const int* in_sizes, int n_in,
                              void* d_out, int out_size) {
    const float* x  = (const float*)d_in[0];
    const float* w1 = (const float*)d_in[1];
    const float* g1 = (const float*)d_in[2];
    const float* b1 = (const float*)d_in[3];
    const float* w2 = (const float*)d_in[4];
    const float* g2 = (const float*)d_in[5];
    const float* b2 = (const float*)d_in[6];
    float* out = (float*)d_out;

    k_prep<<<15, 1024>>>(w1, w2);
    k_pack_x<<<NHW / 4 / 256, 256>>>(x);
    k_conv<<<NN * 7 * (HH / RR), dim3(32, 8)>>>(0);
    k_pack_y<<<NHW / 4 / 256, 256>>>(g1, b1);
    k_conv<<<NN * 7 * (HH / RR), dim3(32, 8)>>>(1);
    k_final<<<NHW / 4 / 256, 256>>>(x, g2, b2, out);
}

// round 7
// speedup vs baseline: 1.4147x; 1.0505x over previous
#include <cuda_runtime.h>
#include <cstdint>

#define NN 16
#define CC 32
#define HH 224
#define WW 224
#define HW (HH * WW)            // 50176
#define NHW (NN * HW)           // 802816
#define PW 226
#define PH 226
#define PHW (PW * PH)           // 51076
#define NPHW (NN * PHW)         // 817216
#define RR 16                   // rows per conv block (224/16 = 14 row-blocks)

// g_y layout: [n][h][group(8)][w][4ch] int8 (halved conv values).
#define GY_IDX(n, h, g, w) (((((size_t)(n) * HH + (h)) * 8 + (g)) * WW + (w)) * 4)

// ---------------- device scratch ----------------
__device__ unsigned    g_bits[NPHW];            // layer-1 input bits (padded)
__device__ signed char g_y[(size_t)NHW * 32];   // conv1 halved output (25.7 MB)
__device__ signed char g_y2[(size_t)NHW * 32];  // conv2 halved output (25.7 MB)
__device__ long long g_sum1[32], g_ssq1[32];    // stats of HALVED values
__device__ long long g_sum2[32], g_ssq2[32];
__device__ unsigned  g_wm0[288];
__device__ unsigned  g_wm1[288];

// ---------------- K0: zero BORDERS of padded bit image + masks + stats ----------
__global__ void k_prep(const float* __restrict__ w1, const float* __restrict__ w2) {
    int i = blockIdx.x * blockDim.x + threadIdx.x;
    if (i < NN * 900) {
        int img = i / 900, r = i % 900;
        int h, w;
        if (r < 226)      { h = 0;            w = r; }
        else if (r < 452) { h = 225;          w = r - 226; }
        else if (r < 676) { h = r - 452 + 1;  w = 0; }
        else              { h = r - 676 + 1;  w = 225; }
        g_bits[(size_t)img * PHW + (size_t)h * PW + w] = 0u;
    }
    if (blockIdx.x == 0) {
        int tid = threadIdx.x;
        if (tid < 288) {
            int o = tid / 9, t = tid % 9;
            unsigned m = 0;
            #pragma unroll
            for (int k = 0; k < 32; k++)
                m |= (w1[(o * 32 + k) * 9 + t] > 0.0f ? 1u : 0u) << k;
            g_wm0[tid] = m;
        } else if (tid < 576) {
            int j = tid - 288;
            int o = j / 9, t = j % 9;
            unsigned m = 0;
            #pragma unroll
            for (int k = 0; k < 32; k++)
                m |= (w2[(o * 32 + k) * 9 + t] > 0.0f ? 1u : 0u) << k;
            g_wm1[j] = m;
        } else if (tid < 608) {
            int o = tid - 576;
            g_sum1[o] = 0; g_ssq1[o] = 0;
            g_sum2[o] = 0; g_ssq2[o] = 0;
        }
    }
}

// ---------------- K1: binarize x -> packed bits ----------------
__global__ __launch_bounds__(256) void k_pack_x(const float* __restrict__ x) {
    int t = blockIdx.x * 256 + threadIdx.x;
    size_t p0 = (size_t)t * 4;
    int n = (int)(p0 / HW);
    int q = (int)(p0 % HW);
    unsigned b0 = 0, b1 = 0, b2 = 0, b3 = 0;
    #pragma unroll
    for (int c = 0; c < 32; c++) {
        const float4 v = *reinterpret_cast<const float4*>(x + ((size_t)(n * 32 + c) * HW + q));
        b0 |= (v.x > 0.0f ? 1u : 0u) << c;
        b1 |= (v.y > 0.0f ? 1u : 0u) << c;
        b2 |= (v.z > 0.0f ? 1u : 0u) << c;
        b3 |= (v.w > 0.0f ? 1u : 0u) << c;
    }
    int h = q / WW, w = q % WW;
    unsigned* d = g_bits + (size_t)n * PHW + (size_t)(h + 1) * PW + (w + 1);
    d[0] = b0; d[1] = b1; d[2] = b2; d[3] = b3;
}

// ---------------- K2: conv layer 1 (global padded bits), halved int8 out --------
__global__ __launch_bounds__(256, 2) void k_conv1() {
    int bid   = blockIdx.x;
    int n     = bid / 98;                 // 7 strips * 14 rowblocks
    int rem   = bid % 98;
    int strip = rem % 7;
    int rb    = rem / 7;
    int w0    = strip * 32;
    int h0    = rb * RR;
    int lane  = threadIdx.x;
    int g     = threadIdx.y;
    int cb    = g * 4;

    unsigned m[4][9];
    #pragma unroll
    for (int j = 0; j < 4; j++)
        #pragma unroll
        for (int t = 0; t < 9; t++)
            m[j][t] = g_wm0[(cb + j) * 9 + t];

    int w = w0 + lane;
    bool eL = (w == 0), eR = (w == WW - 1);

    int cadd[4], rct[4], rcb_[4];
    #pragma unroll
    for (int j = 0; j < 4; j++) {
        int ct[9];
        #pragma unroll
        for (int t = 0; t < 9; t++) ct[t] = 32 - 2 * __popc(m[j][t]);
        cadd[j] = eL ? -(ct[0] + ct[3] + ct[6]) : (eR ? -(ct[2] + ct[5] + ct[8]) : 0);
        rct[j]  = -(ct[0] + ct[1] + ct[2]) + (eL ? ct[0] : 0) + (eR ? ct[2] : 0);
        rcb_[j] = -(ct[6] + ct[7] + ct[8]) + (eL ? ct[6] : 0) + (eR ? ct[8] : 0);
    }

    const unsigned* bp = g_bits + (size_t)n * PHW + (size_t)h0 * PW + w;
    unsigned x0 = bp[0],  x1 = bp[1],      x2 = bp[2];
    unsigned x3 = bp[PW], x4 = bp[PW + 1], x5 = bp[PW + 2];

    bool top = (h0 == 0), bot = (h0 + RR == HH);
    int rs[4] = {0, 0, 0, 0};
    int rq[4] = {0, 0, 0, 0};

    #pragma unroll
    for (int rr = 0; rr < RR; rr++) {
        const unsigned* qp = bp + (size_t)(rr + 2) * PW;
        unsigned x6 = qp[0], x7 = qp[1], x8 = qp[2];

        int hv[4];
        #pragma unroll
        for (int j = 0; j < 4; j++) {
            int ps = __popc(x0 ^ m[j][0]) + __popc(x1 ^ m[j][1]) + __popc(x2 ^ m[j][2])
                   + __popc(x3 ^ m[j][3]) + __popc(x4 ^ m[j][4]) + __popc(x5 ^ m[j][5])
                   + __popc(x6 ^ m[j][6]) + __popc(x7 ^ m[j][7]) + __popc(x8 ^ m[j][8]);
            int acc = 288 - 2 * ps + cadd[j];
            if (rr == 0 && top)      acc += rct[j];
            if (rr == RR - 1 && bot) acc += rcb_[j];
            int h2 = acc >> 1;
            hv[j] = h2;
            rs[j] += h2;
            rq[j] += h2 * h2;
        }
        *reinterpret_cast<char4*>(g_y + GY_IDX(n, h0 + rr, g, w)) =
            make_char4((signed char)hv[0], (signed char)hv[1],
                       (signed char)hv[2], (signed char)hv[3]);

        x0 = x3; x1 = x4; x2 = x5;
        x3 = x6; x4 = x7; x5 = x8;
    }

    #pragma unroll
    for (int j = 0; j < 4; j++) {
        int s = __reduce_add_sync(0xffffffffu, rs[j]);
        int q = __reduce_add_sync(0xffffffffu, rq[j]);
        if (lane == 0) {
            atomicAdd((unsigned long long*)&g_sum1[cb + j], (unsigned long long)(long long)s);
            atomicAdd((unsigned long long*)&g_ssq1[cb + j], (unsigned long long)(long long)q);
        }
    }
}

// ---------------- K3: FUSED threshold(conv1,BN1) + conv layer 2 -----------------
// Stages the (32+2)x(RR+2) halo tile of bits in smem by thresholding g_y (int8,
// halved conv1 values) with the exact integer BN1 sign test, then runs the
// binarized conv from smem. Output -> g_y2 (separate buffer: neighbor blocks
// still read this block's g_y halo).
__global__ __launch_bounds__(256, 2) void k_conv2p(const float* __restrict__ gamma,
                                                   const float* __restrict__ beta) {
    __shared__ unsigned sBits[RR + 2][35];
    __shared__ int      sTc[32];
    __shared__ unsigned sFl[32];
    __shared__ unsigned sT[8], sF[8];

    int lane = threadIdx.x;
    int g    = threadIdx.y;
    int tid  = g * 32 + lane;

    int bid   = blockIdx.x;
    int n     = bid / 98;
    int rem   = bid % 98;
    int strip = rem % 7;
    int rb    = rem / 7;
    int w0    = strip * 32;
    int h0    = rb * RR;

    // ---- thresholds from exact integer stats of layer 1 ----
    if (tid < 32) {
        int o = tid;
        double mean = 2.0 * (double)g_sum1[o] / (double)NHW;
        double var  = 4.0 * (double)g_ssq1[o] / (double)NHW - mean * mean;
        double inv  = rsqrt(var + 1e-5);
        double a    = (double)gamma[o] * inv;
        double cst  = (double)beta[o] - mean * a;
        int T; unsigned f;
        if (a > 0.0)      { T = (int)floor(-cst / (2.0 * a));    f = 0x00u; }
        else if (a < 0.0) { T = (int)ceil(-cst / (2.0 * a)) - 1; f = 0xFFu; }
        else              { T = (cst > 0.0) ? -128 : 127;        f = 0x00u; }
        T = max(-128, min(127, T));
        sTc[o] = T & 0xFF;
        sFl[o] = f;
    }
    __syncthreads();
    if (tid < 8) {
        sT[tid] = (unsigned)sTc[4*tid] | ((unsigned)sTc[4*tid+1] << 8)
                | ((unsigned)sTc[4*tid+2] << 16) | ((unsigned)sTc[4*tid+3] << 24);
        sF[tid] = sFl[4*tid] | (sFl[4*tid+1] << 8) | (sFl[4*tid+2] << 16) | (sFl[4*tid+3] << 24);
    }
    __syncthreads();

    // ---- stage thresholded bits (halo tile) ----
    #pragma unroll
    for (int i = tid; i < (RR + 2) * 34; i += 256) {
        int hl = i / 34, wl = i % 34;
        int h = h0 - 1 + hl, w = w0 - 1 + wl;
        unsigned b = 0;
        if (h >= 0 && h < HH && w >= 0 && w < WW) {
            #pragma unroll
            for (int gg = 0; gg < 8; gg++) {
                unsigned A = *reinterpret_cast<const unsigned*>(g_y + GY_IDX(n, h, gg, w));
                unsigned mm = (__vcmpgts4(A, sT[gg]) ^ sF[gg]) & 0x01010101u;
                b |= ((unsigned)__dp4a(mm, 0x08040201u, 0u)) << (gg * 4);
            }
        }
        sBits[hl][wl] = b;
    }
    __syncthreads();

    // ---- conv from smem ----
    int cb = g * 4;
    unsigned m[4][9];
    #pragma unroll
    for (int j = 0; j < 4; j++)
        #pragma unroll
        for (int t = 0; t < 9; t++)
            m[j][t] = g_wm1[(cb + j) * 9 + t];

    int w = w0 + lane;
    bool eL = (w == 0), eR = (w == WW - 1);

    int cadd[4], rct[4], rcb_[4];
    #pragma unroll
    for (int j = 0; j < 4; j++) {
        int ct[9];
        #pragma unroll
        for (int t = 0; t < 9; t++) ct[t] = 32 - 2 * __popc(m[j][t]);
        cadd[j] = eL ? -(ct[0] + ct[3] + ct[6]) : (eR ? -(ct[2] + ct[5] + ct[8]) : 0);
        rct[j]  = -(ct[0] + ct[1] + ct[2]) + (eL ? ct[0] : 0) + (eR ? ct[2] : 0);
        rcb_[j] = -(ct[6] + ct[7] + ct[8]) + (eL ? ct[6] : 0) + (eR ? ct[8] : 0);
    }

    unsigned x0 = sBits[0][lane], x1 = sBits[0][lane + 1], x2 = sBits[0][lane + 2];
    unsigned x3 = sBits[1][lane], x4 = sBits[1][lane + 1], x5 = sBits[1][lane + 2];

    bool top = (h0 == 0), bot = (h0 + RR == HH);
    int rs[4] = {0, 0, 0, 0};
    int rq[4] = {0, 0, 0, 0};

    #pragma unroll
    for (int rr = 0; rr < RR; rr++) {
        unsigned x6 = sBits[rr + 2][lane];
        unsigned x7 = sBits[rr + 2][lane + 1];
        unsigned x8 = sBits[rr + 2][lane + 2];

        int hv[4];
        #pragma unroll
        for (int j = 0; j < 4; j++) {
            int ps = __popc(x0 ^ m[j][0]) + __popc(x1 ^ m[j][1]) + __popc(x2 ^ m[j][2])
                   + __popc(x3 ^ m[j][3]) + __popc(x4 ^ m[j][4]) + __popc(x5 ^ m[j][5])
                   + __popc(x6 ^ m[j][6]) + __popc(x7 ^ m[j][7]) + __popc(x8 ^ m[j][8]);
            int acc = 288 - 2 * ps + cadd[j];
            if (rr == 0 && top)      acc += rct[j];
            if (rr == RR - 1 && bot) acc += rcb_[j];
            int h2 = acc >> 1;
            hv[j] = h2;
            rs[j] += h2;
            rq[j] += h2 * h2;
        }
        *reinterpret_cast<char4*>(g_y2 + GY_IDX(n, h0 + rr, g, w)) =
            make_char4((signed char)hv[0], (signed char)hv[1],
                       (signed char)hv[2], (signed char)hv[3]);

        x0 = x3; x1 = x4; x2 = x5;
        x3 = x6; x4 = x7; x5 = x8;
    }

    #pragma unroll
    for (int j = 0; j < 4; j++) {
        int s = __reduce_add_sync(0xffffffffu, rs[j]);
        int q = __reduce_add_sync(0xffffffffu, rq[j]);
        if (lane == 0) {
            atomicAdd((unsigned long long*)&g_sum2[cb + j], (unsigned long long)(long long)s);
            atomicAdd((unsigned long long*)&g_ssq2[cb + j], (unsigned long long)(long long)q);
        }
    }
}

// ---------------- K4: out = x + a2*(2*yh2) + c2 (4 px/thread) -------------------
__global__ __launch_bounds__(256) void k_final(const float* __restrict__ x,
                                               const float* __restrict__ gamma,
                                               const float* __restrict__ beta,
                                               float* __restrict__ out) {
    __shared__ float sa[32], sc[32];
    int o = threadIdx.x;
    if (o < 32) {
        double mean = 2.0 * (double)g_sum2[o] / (double)NHW;
        double var  = 4.0 * (double)g_ssq2[o] / (double)NHW - mean * mean;
        double inv  = rsqrt(var + 1e-5);
        double a    = (double)gamma[o] * inv;
        sa[o] = (float)(2.0 * a);
        sc[o] = (float)((double)beta[o] - mean * a);
    }
    __syncthreads();

    int t = blockIdx.x * 256 + threadIdx.x;       // NHW/4 threads
    size_t p0 = (size_t)t * 4;
    int n = (int)(p0 / HW);
    int q = (int)(p0 % HW);
    int h = q / WW, w = q % WW;                   // w % 4 == 0

    #pragma unroll
    for (int g = 0; g < 8; g++) {
        union { uint4 u; signed char s[16]; } A;  // signed char: aarch64 plain char is unsigned
        A.u = *reinterpret_cast<const uint4*>(g_y2 + GY_IDX(n, h, g, w));
        #pragma unroll
        for (int j = 0; j < 4; j++) {
            int c = g * 4 + j;
            float a = sa[c], cc = sc[c];
            size_t xi = (size_t)(n * 32 + c) * HW + q;
            float4 xv = *reinterpret_cast<const float4*>(x + xi);
            float4 o4;
            o4.x = xv.x + fmaf(a, (float)A.s[0 + j],  cc);
            o4.y = xv.y + fmaf(a, (float)A.s[4 + j],  cc);
            o4.z = xv.z + fmaf(a, (float)A.s[8 + j],  cc);
            o4.w = xv.w + fmaf(a, (float)A.s[12 + j], cc);
            *reinterpret_cast<float4*>(out + xi) = o4;
        }
    }
}

// ---------------- launch ----------------
extern "C" void kernel_launch(void* const* d_in, const int* in_sizes, int n_in,
                              void* d_out, int out_size) {
    const float* x  = (const float*)d_in[0];
    const float* w1 = (const float*)d_in[1];
    const float* g1 = (const float*)d_in[2];
    const float* b1 = (const float*)d_in[3];
    const float* w2 = (const float*)d_in[4];
    const float* g2 = (const float*)d_in[5];
    const float* b2 = (const float*)d_in[6];
    float* out = (float*)d_out;

    k_prep<<<15, 1024>>>(w1, w2);
    k_pack_x<<<NHW / 4 / 256, 256>>>(x);
    k_conv1<<<NN * 7 * (HH / RR), dim3(32, 8)>>>();
    k_conv2p<<<NN * 7 * (HH / RR), dim3(32, 8)>>>(g1, b1);
    k_final<<<NHW / 4 / 256, 256>>>(x, g2, b2, out);
}